// round 2
// baseline (speedup 1.0000x reference)
#include <cuda_runtime.h>
#include <cuda_bf16.h>
#include <math.h>

// Problem constants (fixed by setup_inputs)
#define D_DIM   512
#define P_DIM   8
#define Q_DIM   32
#define MARGIN  1.0f
#define L2W     0.005f
#define EPSF    1e-6f
#define MAXN    4096
#define MAXBLK  2048

// Static scratch (no allocations allowed)
__device__ __nv_bfloat16 g_bf[(size_t)MAXN * D_DIM];   // bf16 mirror of batch (4 MB)
__device__ float g_norm[MAXN];
__device__ float g_partials[MAXBLK];
__device__ unsigned int g_count = 0;

__device__ __forceinline__ float warpSum(float v) {
#pragma unroll
    for (int o = 16; o > 0; o >>= 1) v += __shfl_xor_sync(0xffffffffu, v, o);
    return v;
}
__device__ __forceinline__ float warpMax(float v) {
#pragma unroll
    for (int o = 16; o > 0; o >>= 1) v = fmaxf(v, __shfl_xor_sync(0xffffffffu, v, o));
    return v;
}

// ---------------------------------------------------------------------------
// Pass 1: fp32 batch -> bf16 mirror, plus fp32 row norms. Warp-per-row.
// ---------------------------------------------------------------------------
__global__ void __launch_bounds__(128)
convert_kernel(const float* __restrict__ batch, int N) {
    int row  = blockIdx.x * 4 + (threadIdx.x >> 5);
    int lane = threadIdx.x & 31;
    if (row >= N) return;

    const float4* src = (const float4*)(batch + (size_t)row * D_DIM);
    uint2* dst = (uint2*)(g_bf + (size_t)row * D_DIM);

    float nrm = 0.0f;
#pragma unroll
    for (int k = 0; k < 4; k++) {
        float4 v = src[lane + 32 * k];
        nrm += v.x * v.x + v.y * v.y + v.z * v.z + v.w * v.w;
        __nv_bfloat162 lo = __floats2bfloat162_rn(v.x, v.y);
        __nv_bfloat162 hi = __floats2bfloat162_rn(v.z, v.w);
        uint2 o;
        o.x = *(unsigned int*)&lo;
        o.y = *(unsigned int*)&hi;
        dst[lane + 32 * k] = o;
    }
    nrm = warpSum(nrm);
    if (lane == 0) g_norm[row] = sqrtf(nrm);
}

// 8 bf16 (one uint4) vs 8 fp32 anchor values: sum of (a - b + eps)^2
__device__ __forceinline__ float sqd_u4(const float* __restrict__ a, uint4 v) {
    unsigned int w[4] = {v.x, v.y, v.z, v.w};
    float s = 0.0f;
#pragma unroll
    for (int i = 0; i < 4; i++) {
        __nv_bfloat162 p = *reinterpret_cast<__nv_bfloat162*>(&w[i]);
        float2 b = __bfloat1622float2(p);
        float d0 = a[2 * i]     - b.x + EPSF;
        float d1 = a[2 * i + 1] - b.y + EPSF;
        s = fmaf(d0, d0, s);
        s = fmaf(d1, d1, s);
    }
    return s;
}

// ---------------------------------------------------------------------------
// Pass 2: warp-per-anchor distances + logsumexp + fused deterministic mean.
// ---------------------------------------------------------------------------
__global__ void __launch_bounds__(128)
anchor_kernel(const int* __restrict__ anchors,
              const int* __restrict__ pos_idx,
              const int* __restrict__ neg_idx,
              float* __restrict__ out, int N) {
    int gw   = blockIdx.x * 4 + (threadIdx.x >> 5);
    int lane = threadIdx.x & 31;
    int wid  = threadIdx.x >> 5;
    bool active = (gw < N);
    int gwc = active ? gw : 0;

    const uint4* bb = (const uint4*)g_bf;   // 64 uint4 per row
    int l2 = lane * 2;

    // Anchor row -> 16 fp32 registers per lane (lane owns elements [16*lane, 16*lane+16))
    int arow = anchors[gwc];
    size_t ra = (size_t)arow * 64;
    uint4 av0 = bb[ra + l2];
    uint4 av1 = bb[ra + l2 + 1];
    float a[16];
    {
        unsigned int w[8] = {av0.x, av0.y, av0.z, av0.w, av1.x, av1.y, av1.z, av1.w};
#pragma unroll
        for (int i = 0; i < 8; i++) {
            __nv_bfloat162 p = *reinterpret_cast<__nv_bfloat162*>(&w[i]);
            float2 f = __bfloat1622float2(p);
            a[2 * i]     = f.x;
            a[2 * i + 1] = f.y;
        }
    }

    // Lane-distributed neighbor indices
    int pid = pos_idx[gwc * P_DIM + (lane & (P_DIM - 1))];
    int nid = neg_idx[gwc * Q_DIM + lane];

    float dpos = 0.0f, dneg = 0.0f;

#pragma unroll
    for (int k = 0; k < P_DIM; k++) {
        int j = __shfl_sync(0xffffffffu, pid, k);
        size_t rb = (size_t)j * 64;
        uint4 b0 = bb[rb + l2];
        uint4 b1 = bb[rb + l2 + 1];
        float ss = sqd_u4(a, b0) + sqd_u4(a + 8, b1);
        ss = warpSum(ss);
        if (lane == k) dpos = sqrtf(ss);
    }

#pragma unroll 8
    for (int k = 0; k < Q_DIM; k++) {
        int j = __shfl_sync(0xffffffffu, nid, k);
        size_t rb = (size_t)j * 64;
        uint4 b0 = bb[rb + l2];
        uint4 b1 = bb[rb + l2 + 1];
        float ss = sqd_u4(a, b0) + sqd_u4(a + 8, b1);
        ss = warpSum(ss);
        if (lane == k) dneg = sqrtf(ss);
    }

    // logsumexp over pos distances (lanes 0..P-1 hold values)
    float vp = (lane < P_DIM) ? dpos : -1e30f;
    float mp = warpMax(vp);
    float ep = (lane < P_DIM) ? __expf(dpos - mp) : 0.0f;
    float sp = warpSum(ep);
    float pos_term = mp + __logf(sp);

    // logsumexp over MARGIN - neg distances (all 32 lanes)
    float vn = MARGIN - dneg;
    float mn = warpMax(vn);
    float sn = warpSum(__expf(vn - mn));
    float neg_term = mn + __logf(sn);

    // ---- fused deterministic reduction ----
    __shared__ float shp[4];
    __shared__ bool  isLast;
    __shared__ float shw[4];

    float val = 0.0f;
    if (lane == 0 && active)
        val = fmaxf(0.0f, pos_term + neg_term) + L2W * g_norm[gw];
    if (lane == 0) shp[wid] = val;
    __syncthreads();

    if (threadIdx.x == 0) {
        float p = shp[0] + shp[1] + shp[2] + shp[3];
        g_partials[blockIdx.x] = p;
        __threadfence();
        unsigned int old = atomicAdd(&g_count, 1u);
        isLast = (old == gridDim.x - 1);
    }
    __syncthreads();

    if (isLast) {
        int nb = (int)gridDim.x;
        float s = 0.0f;
        for (int i = threadIdx.x; i < nb; i += 128)
            s += g_partials[i];
        s = warpSum(s);
        if (lane == 0) shw[wid] = s;
        __syncthreads();
        if (threadIdx.x == 0) {
            out[0] = (shw[0] + shw[1] + shw[2] + shw[3]) / (float)N;
            g_count = 0;   // reset for next graph replay
        }
    }
}

extern "C" void kernel_launch(void* const* d_in, const int* in_sizes, int n_in,
                              void* d_out, int out_size) {
    const float* batch   = (const float*)d_in[0];
    const int*   anchors = (const int*)d_in[1];
    const int*   pos_idx = (const int*)d_in[2];
    const int*   neg_idx = (const int*)d_in[3];
    int N = in_sizes[1];   // anchors has N elements

    int blocks = (N + 3) / 4;   // warp-per-row / warp-per-anchor, 4 warps per block
    convert_kernel<<<blocks, 128>>>(batch, N);
    anchor_kernel<<<blocks, 128>>>(anchors, pos_idx, neg_idx, (float*)d_out, N);
}

// round 3
// speedup vs baseline: 1.3222x; 1.3222x over previous
#include <cuda_runtime.h>
#include <cuda_bf16.h>
#include <math.h>

// Problem constants (fixed by setup_inputs)
#define D_DIM   512
#define P_DIM   8
#define Q_DIM   32
#define MARGIN  1.0f
#define L2W     0.005f
#define EPSF    1e-6f
#define MAXN    4096
#define MAXBLK  2048

typedef unsigned long long ull;

// Static scratch
__device__ __nv_bfloat16 g_bf[(size_t)MAXN * D_DIM];   // bf16 mirror (4 MB)
__device__ float g_norm[MAXN];    // fp32 ||x|| (for L2 reg term, exact)
__device__ float g_norm2[MAXN];   // |x|^2 from bf16 values
__device__ float g_sum[MAXN];     // sum(x) from bf16 values
__device__ float g_partials[MAXBLK];
__device__ unsigned int g_count = 0;

__device__ __forceinline__ float warpSum(float v) {
#pragma unroll
    for (int o = 16; o > 0; o >>= 1) v += __shfl_xor_sync(0xffffffffu, v, o);
    return v;
}
__device__ __forceinline__ float warpMax(float v) {
#pragma unroll
    for (int o = 16; o > 0; o >>= 1) v = fmaxf(v, __shfl_xor_sync(0xffffffffu, v, o));
    return v;
}

// pack two fp32 into a b64 for f32x2 ops
__device__ __forceinline__ ull pack2(unsigned lo, unsigned hi) {
    ull r;
    asm("mov.b64 %0, {%1, %2};" : "=l"(r) : "r"(lo), "r"(hi));
    return r;
}
// bf16x2 word -> f32x2 b64  (low bf16 -> low f32)
__device__ __forceinline__ ull bf2f32x2(unsigned u) {
    return pack2(u << 16, u & 0xffff0000u);
}
__device__ __forceinline__ void fma2(ull& acc, ull a, ull b) {
    asm("fma.rn.f32x2 %0, %1, %2, %3;" : "=l"(acc) : "l"(a), "l"(b), "l"(acc));
}
__device__ __forceinline__ float hsum2(ull v) {
    float2 f = *reinterpret_cast<float2*>(&v);
    return f.x + f.y;
}

// ---------------------------------------------------------------------------
// Pass 1: fp32 batch -> bf16 mirror + per-row stats. Warp-per-row.
// ---------------------------------------------------------------------------
__global__ void __launch_bounds__(256)
convert_kernel(const float* __restrict__ batch, int N) {
    int row  = blockIdx.x * 8 + (threadIdx.x >> 5);
    int lane = threadIdx.x & 31;
    if (row >= N) return;

    const float4* src = (const float4*)(batch + (size_t)row * D_DIM);
    uint2* dst = (uint2*)(g_bf + (size_t)row * D_DIM);

    float nrm = 0.0f, nrm2 = 0.0f, s = 0.0f;
#pragma unroll
    for (int k = 0; k < 4; k++) {
        float4 v = src[lane + 32 * k];
        nrm += v.x * v.x + v.y * v.y + v.z * v.z + v.w * v.w;
        __nv_bfloat162 lo = __floats2bfloat162_rn(v.x, v.y);
        __nv_bfloat162 hi = __floats2bfloat162_rn(v.z, v.w);
        float2 flo = __bfloat1622float2(lo);
        float2 fhi = __bfloat1622float2(hi);
        nrm2 = fmaf(flo.x, flo.x, nrm2); nrm2 = fmaf(flo.y, flo.y, nrm2);
        nrm2 = fmaf(fhi.x, fhi.x, nrm2); nrm2 = fmaf(fhi.y, fhi.y, nrm2);
        s += flo.x + flo.y + fhi.x + fhi.y;
        uint2 o;
        o.x = *(unsigned int*)&lo;
        o.y = *(unsigned int*)&hi;
        dst[lane + 32 * k] = o;
    }
    nrm  = warpSum(nrm);
    nrm2 = warpSum(nrm2);
    s    = warpSum(s);
    if (lane == 0) {
        g_norm[row]  = sqrtf(nrm);
        g_norm2[row] = nrm2;
        g_sum[row]   = s;
    }
}

// dot of lane's 16 elements of row j against packed anchor apk[8]
__device__ __forceinline__ ull dotrow(const uint4* __restrict__ bb, int j,
                                      int lane, const ull* __restrict__ apk) {
    size_t rb = (size_t)j * 64;
    uint4 b0 = bb[rb + lane];
    uint4 b1 = bb[rb + 32 + lane];
    ull acc = 0;
    fma2(acc, apk[0], bf2f32x2(b0.x));
    fma2(acc, apk[1], bf2f32x2(b0.y));
    fma2(acc, apk[2], bf2f32x2(b0.z));
    fma2(acc, apk[3], bf2f32x2(b0.w));
    fma2(acc, apk[4], bf2f32x2(b1.x));
    fma2(acc, apk[5], bf2f32x2(b1.y));
    fma2(acc, apk[6], bf2f32x2(b1.z));
    fma2(acc, apk[7], bf2f32x2(b1.w));
    return acc;
}

// Reduce 4 per-lane partials (dA..dD) to full warp sums.
// Result: lanes 0-7 hold sum(dA), 8-15 sum(dB), 16-23 sum(dC), 24-31 sum(dD).
__device__ __forceinline__ float quadReduce(float dA, float dB, float dC, float dD, int lane) {
    float tA = dA + __shfl_xor_sync(0xffffffffu, dA, 16);
    float tB = dB + __shfl_xor_sync(0xffffffffu, dB, 16);
    float tC = dC + __shfl_xor_sync(0xffffffffu, dC, 16);
    float tD = dD + __shfl_xor_sync(0xffffffffu, dD, 16);
    float u0 = (lane & 16) ? tC : tA;
    float u1 = (lane & 16) ? tD : tB;
    u0 += __shfl_xor_sync(0xffffffffu, u0, 8);
    u1 += __shfl_xor_sync(0xffffffffu, u1, 8);
    float v = (lane & 8) ? u1 : u0;
    v += __shfl_xor_sync(0xffffffffu, v, 4);
    v += __shfl_xor_sync(0xffffffffu, v, 2);
    v += __shfl_xor_sync(0xffffffffu, v, 1);
    return v;
}

// ---------------------------------------------------------------------------
// Pass 2: warp-per-anchor, dot-product distances, fused deterministic mean.
// ---------------------------------------------------------------------------
__global__ void __launch_bounds__(256)
anchor_kernel(const int* __restrict__ anchors,
              const int* __restrict__ pos_idx,
              const int* __restrict__ neg_idx,
              float* __restrict__ out, int N) {
    int wid  = threadIdx.x >> 5;
    int lane = threadIdx.x & 31;
    int gw   = blockIdx.x * 8 + wid;
    bool active = (gw < N);
    int gwc = active ? gw : 0;

    const uint4* bb = (const uint4*)g_bf;   // 64 uint4 per row

    // Anchor row -> 8 packed f32x2 regs
    int arow = anchors[gwc];
    ull apk[8];
    {
        size_t ra = (size_t)arow * 64;
        uint4 a0 = bb[ra + lane];
        uint4 a1 = bb[ra + 32 + lane];
        apk[0] = bf2f32x2(a0.x); apk[1] = bf2f32x2(a0.y);
        apk[2] = bf2f32x2(a0.z); apk[3] = bf2f32x2(a0.w);
        apk[4] = bf2f32x2(a1.x); apk[5] = bf2f32x2(a1.y);
        apk[6] = bf2f32x2(a1.z); apk[7] = bf2f32x2(a1.w);
    }
    float na2 = g_norm2[arow];
    float sa  = g_sum[arow];
    const float DEPS2 = (float)D_DIM * EPSF * EPSF;

    int r = lane & 7;

    // ---- negatives: lane l owns neg neighbor l ----
    int nid = neg_idx[gwc * Q_DIM + lane];
    float nb2o = g_norm2[nid];
    float sbo  = g_sum[nid];
    float dneg = 0.0f;

#pragma unroll
    for (int it = 0; it < 8; it++) {
        int j0 = __shfl_sync(0xffffffffu, nid, it);
        int j1 = __shfl_sync(0xffffffffu, nid, 8 + it);
        int j2 = __shfl_sync(0xffffffffu, nid, 16 + it);
        int j3 = __shfl_sync(0xffffffffu, nid, 24 + it);
        float dA = hsum2(dotrow(bb, j0, lane, apk));
        float dB = hsum2(dotrow(bb, j1, lane, apk));
        float dC = hsum2(dotrow(bb, j2, lane, apk));
        float dD = hsum2(dotrow(bb, j3, lane, apk));
        float v = quadReduce(dA, dB, dC, dD, lane);
        if (r == it) {
            float d2 = na2 + nb2o - 2.0f * v
                     + 2.0f * EPSF * (sa - sbo) + DEPS2;
            dneg = sqrtf(fmaxf(d2, 0.0f));
        }
    }

    // ---- positives: owner lane 8g+s (s<2) owns pos 2g+s ----
    int pid = pos_idx[gwc * P_DIM + (2 * (lane >> 3) + (lane & 1))];
    float pb2 = g_norm2[pid];
    float ps  = g_sum[pid];
    float dpos = 0.0f;

#pragma unroll
    for (int it = 0; it < 2; it++) {
        int j0 = __shfl_sync(0xffffffffu, pid, it);
        int j1 = __shfl_sync(0xffffffffu, pid, 8 + it);
        int j2 = __shfl_sync(0xffffffffu, pid, 16 + it);
        int j3 = __shfl_sync(0xffffffffu, pid, 24 + it);
        float dA = hsum2(dotrow(bb, j0, lane, apk));
        float dB = hsum2(dotrow(bb, j1, lane, apk));
        float dC = hsum2(dotrow(bb, j2, lane, apk));
        float dD = hsum2(dotrow(bb, j3, lane, apk));
        float v = quadReduce(dA, dB, dC, dD, lane);
        if (r == it) {
            float d2 = na2 + pb2 - 2.0f * v
                     + 2.0f * EPSF * (sa - ps) + DEPS2;
            dpos = sqrtf(fmaxf(d2, 0.0f));
        }
    }

    // logsumexp over pos (valid lanes: (lane&7) < 2, 8 lanes)
    bool pvalid = (r < 2);
    float vp = pvalid ? dpos : -1e30f;
    float mp = warpMax(vp);
    float ep = pvalid ? __expf(dpos - mp) : 0.0f;
    float sp = warpSum(ep);
    float pos_term = mp + __logf(sp);

    // logsumexp over MARGIN - neg (all 32 lanes)
    float vn = MARGIN - dneg;
    float mn = warpMax(vn);
    float sn = warpSum(__expf(vn - mn));
    float neg_term = mn + __logf(sn);

    // ---- fused deterministic reduction ----
    __shared__ float shp[8];
    __shared__ bool  isLast;
    __shared__ float shw[8];

    float val = 0.0f;
    if (lane == 0 && active)
        val = fmaxf(0.0f, pos_term + neg_term) + L2W * g_norm[gw];
    if (lane == 0) shp[wid] = val;
    __syncthreads();

    if (threadIdx.x == 0) {
        float p = 0.0f;
#pragma unroll
        for (int i = 0; i < 8; i++) p += shp[i];
        g_partials[blockIdx.x] = p;
        __threadfence();
        unsigned int old = atomicAdd(&g_count, 1u);
        isLast = (old == gridDim.x - 1);
    }
    __syncthreads();

    if (isLast) {
        int nb = (int)gridDim.x;
        float s = 0.0f;
        for (int i = threadIdx.x; i < nb; i += 256)
            s += g_partials[i];
        s = warpSum(s);
        if (lane == 0) shw[wid] = s;
        __syncthreads();
        if (threadIdx.x == 0) {
            float t = 0.0f;
#pragma unroll
            for (int i = 0; i < 8; i++) t += shw[i];
            out[0] = t / (float)N;
            g_count = 0;   // reset for next graph replay
        }
    }
}

extern "C" void kernel_launch(void* const* d_in, const int* in_sizes, int n_in,
                              void* d_out, int out_size) {
    const float* batch   = (const float*)d_in[0];
    const int*   anchors = (const int*)d_in[1];
    const int*   pos_idx = (const int*)d_in[2];
    const int*   neg_idx = (const int*)d_in[3];
    int N = in_sizes[1];   // anchors has N elements

    int blocks = (N + 7) / 8;   // 8 warps/block, warp-per-row / warp-per-anchor
    convert_kernel<<<blocks, 256>>>(batch, N);
    anchor_kernel<<<blocks, 256>>>(anchors, pos_idx, neg_idx, (float*)d_out, N);
}

// round 4
// speedup vs baseline: 1.3567x; 1.0261x over previous
#include <cuda_runtime.h>
#include <cuda_bf16.h>
#include <math.h>

// Problem constants (fixed by setup_inputs)
#define D_DIM   512
#define P_DIM   8
#define Q_DIM   32
#define MARGIN  1.0f
#define L2W     0.005f
#define EPSF    1e-6f
#define MAXN    4096
#define MAXBLK  2048

typedef unsigned long long ull;

// Static scratch
__device__ __nv_bfloat16 g_bf[(size_t)MAXN * D_DIM];   // bf16 mirror (4 MB)
__device__ float g_norm[MAXN];    // fp32 ||x|| (L2 reg term, exact)
__device__ float g_norm2[MAXN];   // |x|^2 from bf16 values
__device__ float g_sum[MAXN];     // sum(x) from bf16 values
__device__ float g_partials[MAXBLK];
__device__ unsigned int g_count = 0;

__device__ __forceinline__ float warpSum(float v) {
#pragma unroll
    for (int o = 16; o > 0; o >>= 1) v += __shfl_xor_sync(0xffffffffu, v, o);
    return v;
}
__device__ __forceinline__ float warpMax(float v) {
#pragma unroll
    for (int o = 16; o > 0; o >>= 1) v = fmaxf(v, __shfl_xor_sync(0xffffffffu, v, o));
    return v;
}

// pack two fp32 into a b64 for f32x2 ops
__device__ __forceinline__ ull pack2(unsigned lo, unsigned hi) {
    ull r;
    asm("mov.b64 %0, {%1, %2};" : "=l"(r) : "r"(lo), "r"(hi));
    return r;
}
// bf16x2 word -> f32x2 b64  (low bf16 -> low f32)
__device__ __forceinline__ ull bf2f32x2(unsigned u) {
    return pack2(u << 16, u & 0xffff0000u);
}
__device__ __forceinline__ void fma2(ull& acc, ull a, ull b) {
    asm("fma.rn.f32x2 %0, %1, %2, %3;" : "=l"(acc) : "l"(a), "l"(b), "l"(acc));
}
__device__ __forceinline__ float hsum2(ull v) {
    float2 f = *reinterpret_cast<float2*>(&v);
    return f.x + f.y;
}

// ---------------------------------------------------------------------------
// Pass 1: fp32 batch -> bf16 mirror + per-row stats. Warp-per-row.
// ---------------------------------------------------------------------------
__global__ void __launch_bounds__(256)
convert_kernel(const float* __restrict__ batch, int N) {
    int row  = blockIdx.x * 8 + (threadIdx.x >> 5);
    int lane = threadIdx.x & 31;
    if (row >= N) return;

    const float4* src = (const float4*)(batch + (size_t)row * D_DIM);
    uint2* dst = (uint2*)(g_bf + (size_t)row * D_DIM);

    float nrm = 0.0f, nrm2 = 0.0f, s = 0.0f;
#pragma unroll
    for (int k = 0; k < 4; k++) {
        float4 v = src[lane + 32 * k];
        nrm += v.x * v.x + v.y * v.y + v.z * v.z + v.w * v.w;
        __nv_bfloat162 lo = __floats2bfloat162_rn(v.x, v.y);
        __nv_bfloat162 hi = __floats2bfloat162_rn(v.z, v.w);
        float2 flo = __bfloat1622float2(lo);
        float2 fhi = __bfloat1622float2(hi);
        nrm2 = fmaf(flo.x, flo.x, nrm2); nrm2 = fmaf(flo.y, flo.y, nrm2);
        nrm2 = fmaf(fhi.x, fhi.x, nrm2); nrm2 = fmaf(fhi.y, fhi.y, nrm2);
        s += flo.x + flo.y + fhi.x + fhi.y;
        uint2 o;
        o.x = *(unsigned int*)&lo;
        o.y = *(unsigned int*)&hi;
        dst[lane + 32 * k] = o;
    }
    nrm  = warpSum(nrm);
    nrm2 = warpSum(nrm2);
    s    = warpSum(s);
    if (lane == 0) {
        g_norm[row]  = sqrtf(nrm);
        g_norm2[row] = nrm2;
        g_sum[row]   = s;
    }
}

// dot of lane's 16 elements of row j against packed anchor apk[8]
__device__ __forceinline__ ull dotrow(const uint4* __restrict__ bb, int j,
                                      int lane, const ull* __restrict__ apk) {
    size_t rb = (size_t)j * 64;
    uint4 b0 = bb[rb + lane];
    uint4 b1 = bb[rb + 32 + lane];
    ull acc = 0;
    fma2(acc, apk[0], bf2f32x2(b0.x));
    fma2(acc, apk[1], bf2f32x2(b0.y));
    fma2(acc, apk[2], bf2f32x2(b0.z));
    fma2(acc, apk[3], bf2f32x2(b0.w));
    fma2(acc, apk[4], bf2f32x2(b1.x));
    fma2(acc, apk[5], bf2f32x2(b1.y));
    fma2(acc, apk[6], bf2f32x2(b1.z));
    fma2(acc, apk[7], bf2f32x2(b1.w));
    return acc;
}

// Reduce 4 per-lane partials (dA..dD) to full warp sums.
// Result: lane groups 0-7 / 8-15 / 16-23 / 24-31 hold sum(dA..dD) resp.
__device__ __forceinline__ float quadReduce(float dA, float dB, float dC, float dD, int lane) {
    float tA = dA + __shfl_xor_sync(0xffffffffu, dA, 16);
    float tB = dB + __shfl_xor_sync(0xffffffffu, dB, 16);
    float tC = dC + __shfl_xor_sync(0xffffffffu, dC, 16);
    float tD = dD + __shfl_xor_sync(0xffffffffu, dD, 16);
    float u0 = (lane & 16) ? tC : tA;
    float u1 = (lane & 16) ? tD : tB;
    u0 += __shfl_xor_sync(0xffffffffu, u0, 8);
    u1 += __shfl_xor_sync(0xffffffffu, u1, 8);
    float v = (lane & 8) ? u1 : u0;
    v += __shfl_xor_sync(0xffffffffu, v, 4);
    v += __shfl_xor_sync(0xffffffffu, v, 2);
    v += __shfl_xor_sync(0xffffffffu, v, 1);
    return v;
}

// ---------------------------------------------------------------------------
// Pass 2: TWO warps per anchor (occupancy 2x). Block = 8 warps = 4 anchors.
// Each warp computes 16 neg + 4 pos dot products (5 quad-iterations),
// writes raw dots to shared; warps 0-3 then do the per-anchor logsumexp.
// ---------------------------------------------------------------------------
__global__ void __launch_bounds__(256)
anchor_kernel(const int* __restrict__ anchors,
              const int* __restrict__ pos_idx,
              const int* __restrict__ neg_idx,
              float* __restrict__ out, int N) {
    int wid  = threadIdx.x >> 5;
    int lane = threadIdx.x & 31;
    int a    = wid >> 1;            // anchor slot in block (0..3)
    int sub  = wid & 1;             // which half of this anchor's work
    int gw   = blockIdx.x * 4 + a;  // global anchor index
    bool active = (gw < N);
    int gwc = active ? gw : 0;

    __shared__ float sm_neg[4][32];
    __shared__ float sm_pos[4][8];
    __shared__ float shp[4];
    __shared__ float shw[8];
    __shared__ bool  isLast;

    const uint4* bb = (const uint4*)g_bf;   // 64 uint4 per row

    // Anchor row -> 8 packed f32x2 regs
    int arow = anchors[gwc];
    ull apk[8];
    {
        size_t ra = (size_t)arow * 64;
        uint4 a0 = bb[ra + lane];
        uint4 a1 = bb[ra + 32 + lane];
        apk[0] = bf2f32x2(a0.x); apk[1] = bf2f32x2(a0.y);
        apk[2] = bf2f32x2(a0.z); apk[3] = bf2f32x2(a0.w);
        apk[4] = bf2f32x2(a1.x); apk[5] = bf2f32x2(a1.y);
        apk[6] = bf2f32x2(a1.z); apk[7] = bf2f32x2(a1.w);
    }

    int r = lane & 7;
    int g = lane >> 3;

    // ---- 16 negatives for this half ----
    int nid = neg_idx[gwc * Q_DIM + sub * 16 + (lane & 15)];
#pragma unroll
    for (int it = 0; it < 4; it++) {
        int j0 = __shfl_sync(0xffffffffu, nid, it);
        int j1 = __shfl_sync(0xffffffffu, nid, 4 + it);
        int j2 = __shfl_sync(0xffffffffu, nid, 8 + it);
        int j3 = __shfl_sync(0xffffffffu, nid, 12 + it);
        float dA = hsum2(dotrow(bb, j0, lane, apk));
        float dB = hsum2(dotrow(bb, j1, lane, apk));
        float dC = hsum2(dotrow(bb, j2, lane, apk));
        float dD = hsum2(dotrow(bb, j3, lane, apk));
        float v = quadReduce(dA, dB, dC, dD, lane);
        if (r == it) sm_neg[a][sub * 16 + 4 * g + it] = v;
    }

    // ---- 4 positives for this half ----
    int pid = pos_idx[gwc * P_DIM + sub * 4 + (lane & 3)];
    {
        int j0 = __shfl_sync(0xffffffffu, pid, 0);
        int j1 = __shfl_sync(0xffffffffu, pid, 1);
        int j2 = __shfl_sync(0xffffffffu, pid, 2);
        int j3 = __shfl_sync(0xffffffffu, pid, 3);
        float dA = hsum2(dotrow(bb, j0, lane, apk));
        float dB = hsum2(dotrow(bb, j1, lane, apk));
        float dC = hsum2(dotrow(bb, j2, lane, apk));
        float dD = hsum2(dotrow(bb, j3, lane, apk));
        float v = quadReduce(dA, dB, dC, dD, lane);
        if (r == 0) sm_pos[a][sub * 4 + g] = v;
    }
    __syncthreads();

    // ---- warps 0-3: logsumexp for anchor `wid` ----
    if (wid < 4) {
        int gw2 = blockIdx.x * 4 + wid;
        bool act2 = (gw2 < N);
        int gwc2 = act2 ? gw2 : 0;
        int ar2 = anchors[gwc2];
        float na2 = g_norm2[ar2];
        float sa  = g_sum[ar2];
        const float DEPS2 = (float)D_DIM * EPSF * EPSF;

        // negatives: lane l owns neg l
        int nj = neg_idx[gwc2 * Q_DIM + lane];
        float vdot = sm_neg[wid][lane];
        float d2n = na2 + g_norm2[nj] - 2.0f * vdot
                  + 2.0f * EPSF * (sa - g_sum[nj]) + DEPS2;
        float dneg = sqrtf(fmaxf(d2n, 0.0f));

        // positives: lanes 0-7
        float dpos = 0.0f;
        if (lane < P_DIM) {
            int pj = pos_idx[gwc2 * P_DIM + lane];
            float pdot = sm_pos[wid][lane];
            float d2p = na2 + g_norm2[pj] - 2.0f * pdot
                      + 2.0f * EPSF * (sa - g_sum[pj]) + DEPS2;
            dpos = sqrtf(fmaxf(d2p, 0.0f));
        }

        float vp = (lane < P_DIM) ? dpos : -1e30f;
        float mp = warpMax(vp);
        float ep = (lane < P_DIM) ? __expf(dpos - mp) : 0.0f;
        float sp = warpSum(ep);
        float pos_term = mp + __logf(sp);

        float vn = MARGIN - dneg;
        float mn = warpMax(vn);
        float sn = warpSum(__expf(vn - mn));
        float neg_term = mn + __logf(sn);

        float val = 0.0f;
        if (lane == 0 && act2)
            val = fmaxf(0.0f, pos_term + neg_term) + L2W * g_norm[gw2];
        if (lane == 0) shp[wid] = val;
    }
    __syncthreads();

    // ---- fused deterministic reduction ----
    if (threadIdx.x == 0) {
        float p = shp[0] + shp[1] + shp[2] + shp[3];
        g_partials[blockIdx.x] = p;
        __threadfence();
        unsigned int old = atomicAdd(&g_count, 1u);
        isLast = (old == gridDim.x - 1);
    }
    __syncthreads();

    if (isLast) {
        int nb = (int)gridDim.x;
        float s = 0.0f;
        for (int i = threadIdx.x; i < nb; i += 256)
            s += g_partials[i];
        s = warpSum(s);
        if (lane == 0) shw[wid] = s;
        __syncthreads();
        if (threadIdx.x == 0) {
            float t = 0.0f;
#pragma unroll
            for (int i = 0; i < 8; i++) t += shw[i];
            out[0] = t / (float)N;
            g_count = 0;   // reset for next graph replay
        }
    }
}

extern "C" void kernel_launch(void* const* d_in, const int* in_sizes, int n_in,
                              void* d_out, int out_size) {
    const float* batch   = (const float*)d_in[0];
    const int*   anchors = (const int*)d_in[1];
    const int*   pos_idx = (const int*)d_in[2];
    const int*   neg_idx = (const int*)d_in[3];
    int N = in_sizes[1];   // anchors has N elements

    int cblocks = (N + 7) / 8;
    convert_kernel<<<cblocks, 256>>>(batch, N);
    int ablocks = (N + 3) / 4;   // 4 anchors per block, 2 warps per anchor
    anchor_kernel<<<ablocks, 256>>>(anchors, pos_idx, neg_idx, (float*)d_out, N);
}

// round 6
// speedup vs baseline: 1.4895x; 1.0979x over previous
#include <cuda_runtime.h>
#include <cuda_bf16.h>
#include <math.h>

// Problem constants (fixed by setup_inputs)
#define D_DIM   512
#define P_DIM   8
#define Q_DIM   32
#define MARGIN  1.0f
#define L2W     0.005f
#define EPSF    1e-6f
#define MAXN    4096
#define MAXBLK  2048

typedef unsigned long long ull;

// Static scratch
__device__ __nv_bfloat16 g_bf[(size_t)MAXN * D_DIM];   // bf16 mirror (4 MB)
__device__ float g_norm[MAXN];    // fp32 ||x|| (L2 reg term, exact)
__device__ float g_norm2[MAXN];   // |x'|^2 of REPRESENTED values
__device__ float g_sum[MAXN];     // sum(x') of REPRESENTED values
__device__ float g_partials[MAXBLK];
__device__ unsigned int g_count = 0;

__device__ __forceinline__ float warpSum(float v) {
#pragma unroll
    for (int o = 16; o > 0; o >>= 1) v += __shfl_xor_sync(0xffffffffu, v, o);
    return v;
}
__device__ __forceinline__ float warpMax(float v) {
#pragma unroll
    for (int o = 16; o > 0; o >>= 1) v = fmaxf(v, __shfl_xor_sync(0xffffffffu, v, o));
    return v;
}

// pack two fp32 bit patterns into a b64 for f32x2 ops
__device__ __forceinline__ ull pack2(unsigned lo, unsigned hi) {
    ull r;
    asm("mov.b64 %0, {%1, %2};" : "=l"(r) : "r"(lo), "r"(hi));
    return r;
}
// bf16x2 word -> f32x2: low bf16 exact (u<<16), high bf16 with garbage low
// mantissa bits (reinterpret u). Stats are computed from the SAME representation.
__device__ __forceinline__ ull bfpair(unsigned u) {
    return pack2(u << 16, u);
}
__device__ __forceinline__ void fma2(ull& acc, ull a, ull b) {
    asm("fma.rn.f32x2 %0, %1, %2, %3;" : "=l"(acc) : "l"(a), "l"(b), "l"(acc));
}
__device__ __forceinline__ float hsum2(ull v) {
    float2 f = *reinterpret_cast<float2*>(&v);
    return f.x + f.y;
}

// ---------------------------------------------------------------------------
// Pass 1: fp32 batch -> bf16 mirror + per-row stats of the represented values.
// ---------------------------------------------------------------------------
__global__ void __launch_bounds__(256)
convert_kernel(const float* __restrict__ batch, int N) {
    int row  = blockIdx.x * 8 + (threadIdx.x >> 5);
    int lane = threadIdx.x & 31;
    if (row >= N) return;

    const float4* src = (const float4*)(batch + (size_t)row * D_DIM);
    uint2* dst = (uint2*)(g_bf + (size_t)row * D_DIM);

    float nrm = 0.0f, nrm2 = 0.0f, s = 0.0f;
#pragma unroll
    for (int k = 0; k < 4; k++) {
        float4 v = src[lane + 32 * k];
        nrm += v.x * v.x + v.y * v.y + v.z * v.z + v.w * v.w;
        __nv_bfloat162 lo = __floats2bfloat162_rn(v.x, v.y);
        __nv_bfloat162 hi = __floats2bfloat162_rn(v.z, v.w);
        unsigned u0 = *(unsigned*)&lo;
        unsigned u1 = *(unsigned*)&hi;
        // represented values (must match anchor-kernel unpack exactly)
        float xv = __uint_as_float(u0 << 16);
        float yv = __uint_as_float(u0);
        float zv = __uint_as_float(u1 << 16);
        float wv = __uint_as_float(u1);
        nrm2 = fmaf(xv, xv, nrm2); nrm2 = fmaf(yv, yv, nrm2);
        nrm2 = fmaf(zv, zv, nrm2); nrm2 = fmaf(wv, wv, nrm2);
        s += xv + yv + zv + wv;
        uint2 o; o.x = u0; o.y = u1;
        dst[lane + 32 * k] = o;
    }
    nrm  = warpSum(nrm);
    nrm2 = warpSum(nrm2);
    s    = warpSum(s);
    if (lane == 0) {
        g_norm[row]  = sqrtf(nrm);
        g_norm2[row] = nrm2;
        g_sum[row]   = s;
    }
}

// per-lane partial dot of row j (lane's 16 elements) against packed anchor
__device__ __forceinline__ float dotrow(const uint4* __restrict__ bb, int j,
                                        int lane, const ull* __restrict__ apk) {
    size_t rb = (size_t)j * 64;
    uint4 b0 = bb[rb + lane];
    uint4 b1 = bb[rb + 32 + lane];
    ull acc = 0;
    fma2(acc, apk[0], bfpair(b0.x));
    fma2(acc, apk[1], bfpair(b0.y));
    fma2(acc, apk[2], bfpair(b0.z));
    fma2(acc, apk[3], bfpair(b0.w));
    fma2(acc, apk[4], bfpair(b1.x));
    fma2(acc, apk[5], bfpair(b1.y));
    fma2(acc, apk[6], bfpair(b1.z));
    fma2(acc, apk[7], bfpair(b1.w));
    return hsum2(acc);
}

// Reduce 4 per-lane partials to warp sums:
// lanes 0-7 get sum(dA), 8-15 sum(dB), 16-23 sum(dC), 24-31 sum(dD).
__device__ __forceinline__ float quadReduce(float dA, float dB, float dC, float dD, int lane) {
    float tA = dA + __shfl_xor_sync(0xffffffffu, dA, 16);
    float tB = dB + __shfl_xor_sync(0xffffffffu, dB, 16);
    float tC = dC + __shfl_xor_sync(0xffffffffu, dC, 16);
    float tD = dD + __shfl_xor_sync(0xffffffffu, dD, 16);
    float u0 = (lane & 16) ? tC : tA;
    float u1 = (lane & 16) ? tD : tB;
    u0 += __shfl_xor_sync(0xffffffffu, u0, 8);
    u1 += __shfl_xor_sync(0xffffffffu, u1, 8);
    float v = (lane & 8) ? u1 : u0;
    v += __shfl_xor_sync(0xffffffffu, v, 4);
    v += __shfl_xor_sync(0xffffffffu, v, 2);
    v += __shfl_xor_sync(0xffffffffu, v, 1);
    return v;
}

// ---------------------------------------------------------------------------
// Pass 2: warp-per-anchor (128-thread blocks), uniform-index gathers,
// deferred distance epilogue, fused deterministic mean.
// ---------------------------------------------------------------------------
__global__ void __launch_bounds__(128)
anchor_kernel(const int* __restrict__ anchors,
              const int* __restrict__ pos_idx,
              const int* __restrict__ neg_idx,
              float* __restrict__ out, int N) {
    int wid  = threadIdx.x >> 5;
    int lane = threadIdx.x & 31;
    int gw   = blockIdx.x * 4 + wid;
    bool active = (gw < N);
    int gwc = active ? gw : 0;

    const uint4* bb = (const uint4*)g_bf;   // 64 uint4 per row

    // Anchor row -> 8 packed f32x2 regs
    int arow = __ldg(anchors + gwc);
    ull apk[8];
    {
        size_t ra = (size_t)arow * 64;
        uint4 a0 = bb[ra + lane];
        uint4 a1 = bb[ra + 32 + lane];
        apk[0] = bfpair(a0.x); apk[1] = bfpair(a0.y);
        apk[2] = bfpair(a0.z); apk[3] = bfpair(a0.w);
        apk[4] = bfpair(a1.x); apk[5] = bfpair(a1.y);
        apk[6] = bfpair(a1.z); apk[7] = bfpair(a1.w);
    }

    const int* nbase = neg_idx + gwc * Q_DIM;
    const int* pbase = pos_idx + gwc * P_DIM;
    int r = lane & 7;
    int g = lane >> 3;

    float ndot = 0.0f;   // after loop: lane L owns dot(anchor, neg[L])
    float pdot = 0.0f;   // lanes with r<2: dot(anchor, pos[2g+r])

#pragma unroll
    for (int it = 0; it < 8; it++) {
        int j0 = __ldg(nbase + it);
        int j1 = __ldg(nbase + 8 + it);
        int j2 = __ldg(nbase + 16 + it);
        int j3 = __ldg(nbase + 24 + it);
        float dA = dotrow(bb, j0, lane, apk);
        float dB = dotrow(bb, j1, lane, apk);
        float dC = dotrow(bb, j2, lane, apk);
        float dD = dotrow(bb, j3, lane, apk);
        float v = quadReduce(dA, dB, dC, dD, lane);
        if (r == it) ndot = v;
    }

#pragma unroll
    for (int it = 0; it < 2; it++) {
        int j0 = __ldg(pbase + it);
        int j1 = __ldg(pbase + 2 + it);
        int j2 = __ldg(pbase + 4 + it);
        int j3 = __ldg(pbase + 6 + it);
        float dA = dotrow(bb, j0, lane, apk);
        float dB = dotrow(bb, j1, lane, apk);
        float dC = dotrow(bb, j2, lane, apk);
        float dD = dotrow(bb, j3, lane, apk);
        float v = quadReduce(dA, dB, dC, dD, lane);
        if (r == it) pdot = v;
    }

    // ---- distances from dots (per-lane, out of the hot loop) ----
    float na2 = g_norm2[arow];
    float sa  = g_sum[arow];
    const float DEPS2 = (float)D_DIM * EPSF * EPSF;

    int nj = nbase[lane];
    float d2n = na2 + g_norm2[nj] - 2.0f * ndot
              + 2.0f * EPSF * (sa - g_sum[nj]) + DEPS2;
    float dneg = sqrtf(fmaxf(d2n, 0.0f));

    bool pvalid = (r < 2);
    int pj = pbase[2 * g + (pvalid ? r : 0)];
    float d2p = na2 + g_norm2[pj] - 2.0f * pdot
              + 2.0f * EPSF * (sa - g_sum[pj]) + DEPS2;
    float dpos = sqrtf(fmaxf(d2p, 0.0f));

    // logsumexp over pos (8 owner lanes) and MARGIN - neg (all 32)
    float vp = pvalid ? dpos : -1e30f;
    float mp = warpMax(vp);
    float ep = pvalid ? __expf(dpos - mp) : 0.0f;
    float sp = warpSum(ep);
    float pos_term = mp + __logf(sp);

    float vn = MARGIN - dneg;
    float mn = warpMax(vn);
    float sn = warpSum(__expf(vn - mn));
    float neg_term = mn + __logf(sn);

    // ---- fused deterministic reduction ----
    __shared__ float shp[4];
    __shared__ float shw[4];
    __shared__ bool  isLast;

    float val = 0.0f;
    if (lane == 0 && active)
        val = fmaxf(0.0f, pos_term + neg_term) + L2W * g_norm[gw];
    if (lane == 0) shp[wid] = val;
    __syncthreads();

    if (threadIdx.x == 0) {
        g_partials[blockIdx.x] = shp[0] + shp[1] + shp[2] + shp[3];
        __threadfence();
        unsigned int old = atomicAdd(&g_count, 1u);
        isLast = (old == gridDim.x - 1);
    }
    __syncthreads();

    if (isLast) {
        int nb = (int)gridDim.x;
        float s = 0.0f;
        for (int i = threadIdx.x; i < nb; i += 128)
            s += g_partials[i];
        s = warpSum(s);
        if (lane == 0) shw[wid] = s;
        __syncthreads();
        if (threadIdx.x == 0) {
            out[0] = (shw[0] + shw[1] + shw[2] + shw[3]) / (float)N;
            g_count = 0;   // reset for next graph replay
        }
    }
}

extern "C" void kernel_launch(void* const* d_in, const int* in_sizes, int n_in,
                              void* d_out, int out_size) {
    const float* batch   = (const float*)d_in[0];
    const int*   anchors = (const int*)d_in[1];
    const int*   pos_idx = (const int*)d_in[2];
    const int*   neg_idx = (const int*)d_in[3];
    int N = in_sizes[1];   // anchors has N elements

    int cblocks = (N + 7) / 8;
    convert_kernel<<<cblocks, 256>>>(batch, N);
    int ablocks = (N + 3) / 4;   // warp-per-anchor, 4 warps/block
    anchor_kernel<<<ablocks, 128>>>(anchors, pos_idx, neg_idx, (float*)d_out, N);
}